// round 15
// baseline (speedup 1.0000x reference)
#include <cuda_runtime.h>
#include <cstdint>

#define DFEAT 128
#define DF4   (DFEAT / 4)
#define NMAX  50048
#define EMAX  800000
#define SCAN_TB 256
#define NBMAX   ((NMAX + SCAN_TB - 1) / SCAN_TB)

// pre-split tf32 weight offsets (u32 elements)
#define OFF_WL0 0
#define OFF_WR0 16384
#define OFF_WL1 32768
#define OFF_WR1 49152
#define OFF_WL2 65536
#define OFF_WR2 73728
#define W_TOTAL 81920

// Scratch in __device__ globals, device-side references only.
__device__ int      g_cnt[NMAX];
__device__ int      g_cursor[NMAX];
__device__ int      g_rowptr[NMAX + 1];
__device__ int      g_col[EMAX];
__device__ int      g_bsum[NBMAX + 32];
__device__ int      g_boff[NBMAX + 32];
__device__ float    g_invdeg[NMAX];
__device__ uint32_t g_whi[W_TOTAL];
__device__ uint32_t g_wlo[W_TOTAL];
__device__ float4   g_agg[(size_t)NMAX * DF4];
__device__ float4   g_h1 [(size_t)NMAX * DF4];
__device__ float4   g_h2 [(size_t)NMAX * DF4];

__device__ __forceinline__ uint32_t f2tf32(float x) {
    uint32_t r; asm("cvt.rna.tf32.f32 %0, %1;" : "=r"(r) : "f"(x)); return r;
}

// ---------------------------------------------------------------- weight pre-split
__global__ void presplit_kernel(const float* __restrict__ Wl0, const float* __restrict__ Wr0,
                                const float* __restrict__ Wl1, const float* __restrict__ Wr1,
                                const float* __restrict__ Wl2, const float* __restrict__ Wr2) {
    int i = blockIdx.x * blockDim.x + threadIdx.x;
    if (i >= W_TOTAL) return;
    const float* src; int idx;
    if (i < 32768)      { src = (i < 16384) ? Wl0 : Wr0; idx = i & 16383; }
    else if (i < 65536) { src = (i < 49152) ? Wl1 : Wr1; idx = (i - 32768) & 16383; }
    else                { src = (i < 73728) ? Wl2 : Wr2; idx = (i - 65536) & 8191; }
    float w = src[idx];
    uint32_t hi = f2tf32(w);
    g_whi[i] = hi;
    g_wlo[i] = f2tf32(w - __uint_as_float(hi));
}

// ---------------------------------------------------------------- CSR build
__global__ void zero_cnt_kernel(int n) {
    int i = blockIdx.x * blockDim.x + threadIdx.x;
    if (i < n) g_cnt[i] = 0;
}

__global__ void count_kernel(const int* __restrict__ dst, int E) {
    int e = blockIdx.x * blockDim.x + threadIdx.x;
    if (e < E) atomicAdd(&g_cnt[dst[e]], 1);
}

__global__ __launch_bounds__(SCAN_TB)
void block_sum_kernel(int n) {
    __shared__ int ws[SCAN_TB / 32];
    int i = blockIdx.x * SCAN_TB + threadIdx.x;
    int v = (i < n) ? g_cnt[i] : 0;
#pragma unroll
    for (int o = 16; o > 0; o >>= 1) v += __shfl_down_sync(0xffffffffu, v, o);
    if ((threadIdx.x & 31) == 0) ws[threadIdx.x >> 5] = v;
    __syncthreads();
    if (threadIdx.x < SCAN_TB / 32) {
        int s = ws[threadIdx.x];
#pragma unroll
        for (int o = SCAN_TB / 64; o > 0; o >>= 1)
            s += __shfl_down_sync(0xffffffffu, s, o);
        if (threadIdx.x == 0) g_bsum[blockIdx.x] = s;
    }
}

__global__ __launch_bounds__(SCAN_TB)
void scan_bsum_kernel(int nb, int n) {
    __shared__ int sm[SCAN_TB];
    int t = threadIdx.x;
    int v = (t < nb) ? g_bsum[t] : 0;
    sm[t] = v;
    __syncthreads();
#pragma unroll
    for (int o = 1; o < SCAN_TB; o <<= 1) {
        int u = (t >= o) ? sm[t - o] : 0;
        __syncthreads();
        sm[t] += u;
        __syncthreads();
    }
    if (t < nb) g_boff[t] = sm[t] - v;
    if (t == SCAN_TB - 1) g_rowptr[n] = sm[SCAN_TB - 1];
}

__global__ __launch_bounds__(SCAN_TB)
void rowptr_kernel(int n) {
    __shared__ int sm[SCAN_TB];
    int t = threadIdx.x;
    int i = blockIdx.x * SCAN_TB + t;
    int v = (i < n) ? g_cnt[i] : 0;
    sm[t] = v;
    __syncthreads();
#pragma unroll
    for (int o = 1; o < SCAN_TB; o <<= 1) {
        int u = (t >= o) ? sm[t - o] : 0;
        __syncthreads();
        sm[t] += u;
        __syncthreads();
    }
    if (i < n) {
        g_rowptr[i] = g_boff[blockIdx.x] + sm[t] - v;
        g_invdeg[i] = 1.0f / (float)max(v, 1);
        g_cursor[i] = 0;
    }
}

__global__ void fill_kernel(const int* __restrict__ src,
                            const int* __restrict__ dst, int E) {
    int e = blockIdx.x * blockDim.x + threadIdx.x;
    if (e >= E) return;
    int d = dst[e];
    int pos = atomicAdd(&g_cursor[d], 1);
    g_col[g_rowptr[d] + pos] = src[e];
}

// ---------------------------------------------------------------- aggregation
// One warp per node. Inner gathers issued in PREDICATED 8-wide batches:
// unconditionally unrolled loads guarded by j<m -> MLP=8 even at deg~16.
__global__ __launch_bounds__(256)
void aggregate_csr(const float4* __restrict__ x4, int layer, int N) {
    const float4* h4 = (layer == 0) ? x4 : (layer == 1) ? g_h1 : g_h2;

    int node = blockIdx.x * (blockDim.x >> 5) + (threadIdx.x >> 5);
    int lane = threadIdx.x & 31;
    if (node >= N) return;

    int beg = g_rowptr[node], end = g_rowptr[node + 1];
    float id = g_invdeg[node];

    float4 acc0 = make_float4(0.f, 0.f, 0.f, 0.f);
    float4 acc1 = make_float4(0.f, 0.f, 0.f, 0.f);

    for (int i0 = beg; i0 < end; i0 += 32) {
        int nbr = (i0 + lane < end) ? g_col[i0 + lane] : 0;
        int m = min(32, end - i0);
        for (int j0 = 0; j0 < m; j0 += 8) {
            float4 v[8];
#pragma unroll
            for (int jj = 0; jj < 8; jj++) {
                int j = j0 + jj;
                int s = __shfl_sync(0xffffffffu, nbr, j);
                v[jj] = (j < m) ? h4[(size_t)s * DF4 + lane]
                                : make_float4(0.f, 0.f, 0.f, 0.f);
            }
#pragma unroll
            for (int jj = 0; jj < 8; jj += 2) {
                acc0.x += v[jj].x;     acc0.y += v[jj].y;
                acc0.z += v[jj].z;     acc0.w += v[jj].w;
                acc1.x += v[jj + 1].x; acc1.y += v[jj + 1].y;
                acc1.z += v[jj + 1].z; acc1.w += v[jj + 1].w;
            }
        }
    }

    float4 acc = make_float4((acc0.x + acc1.x) * id, (acc0.y + acc1.y) * id,
                             (acc0.z + acc1.z) * id, (acc0.w + acc1.w) * id);
    g_agg[(size_t)node * DF4 + lane] = acc;
}

// ---------------------------------------------------------------- tensor-core GEMM
// out = relu?( agg @ Wl^T + bl + h @ Wr^T ), fp32 via 3xTF32 HMMA.
// B operands come PRE-SPLIT (hi/lo tf32) from g_whi/g_wlo — no per-block
// weight split ALU. A split stays in-kernel (amortized over NT tiles).
__device__ __forceinline__ void tf32_split(float x, uint32_t& hi, uint32_t& lo) {
    hi = f2tf32(x);
    lo = f2tf32(x - __uint_as_float(hi));
}
__device__ __forceinline__ void mma8(float* c, uint32_t a0, uint32_t a1,
                                     uint32_t a2, uint32_t a3,
                                     uint32_t b0, uint32_t b1) {
    asm("mma.sync.aligned.m16n8k8.row.col.f32.tf32.tf32.f32 "
        "{%0,%1,%2,%3}, {%4,%5,%6,%7}, {%8,%9}, {%0,%1,%2,%3};"
        : "+f"(c[0]), "+f"(c[1]), "+f"(c[2]), "+f"(c[3])
        : "r"(a0), "r"(a1), "r"(a2), "r"(a3), "r"(b0), "r"(b1));
}

template<int DOUT, bool RELU>
__global__ __launch_bounds__(256)
void sage_gemm_tc(const float4* __restrict__ x4,
                  const float* __restrict__ bl,
                  int wloff, int wroff,
                  float4* __restrict__ dout4, int layer, int N) {
    const float* hin = (const float*)((layer == 0) ? x4 : (layer == 1) ? g_h1 : g_h2);
    float*       out = (float*)((layer == 0) ? g_h1 : (layer == 1) ? g_h2 : dout4);
    const float* agg = (const float*)g_agg;

    constexpr int NW_N = 2;
    constexpr int WN   = DOUT / NW_N;
    constexpr int NT   = WN / 8;

    const int warp = threadIdx.x >> 5;
    const int lane = threadIdx.x & 31;
    const int g    = lane >> 2;
    const int tg   = lane & 3;

    const int wm = warp / NW_N;
    const int wn = warp % NW_N;
    const int rowbase = blockIdx.x * 128 + wm * 32;
    const int colbase = wn * WN;

    float acc[2][NT][4];
#pragma unroll
    for (int m = 0; m < 2; m++)
#pragma unroll
        for (int t = 0; t < NT; t++)
#pragma unroll
            for (int i = 0; i < 4; i++) acc[m][t][i] = 0.f;

#pragma unroll
    for (int p = 0; p < 2; p++) {
        const float*    A   = p ? hin : agg;
        const uint32_t* Bhi = g_whi + (p ? wroff : wloff);
        const uint32_t* Blo = g_wlo + (p ? wroff : wloff);

        for (int k0 = 0; k0 < DFEAT; k0 += 8) {
            uint32_t ahi[2][4], alo[2][4];
#pragma unroll
            for (int m = 0; m < 2; m++) {
                int ra = min(rowbase + m * 16 + g, N - 1);
                int rb = min(rowbase + m * 16 + g + 8, N - 1);
                float v0 = A[(size_t)ra * DFEAT + k0 + tg];
                float v1 = A[(size_t)rb * DFEAT + k0 + tg];
                float v2 = A[(size_t)ra * DFEAT + k0 + tg + 4];
                float v3 = A[(size_t)rb * DFEAT + k0 + tg + 4];
                tf32_split(v0, ahi[m][0], alo[m][0]);
                tf32_split(v1, ahi[m][1], alo[m][1]);
                tf32_split(v2, ahi[m][2], alo[m][2]);
                tf32_split(v3, ahi[m][3], alo[m][3]);
            }
#pragma unroll
            for (int t = 0; t < NT; t++) {
                int n0 = colbase + t * 8;
                size_t wi0 = (size_t)(n0 + g) * DFEAT + k0 + tg;
                uint32_t b0h = Bhi[wi0],     b1h = Bhi[wi0 + 4];
                uint32_t b0l = Blo[wi0],     b1l = Blo[wi0 + 4];
#pragma unroll
                for (int m = 0; m < 2; m++) {
                    mma8(acc[m][t], ahi[m][0], ahi[m][1], ahi[m][2], ahi[m][3], b0h, b1h);
                    mma8(acc[m][t], ahi[m][0], ahi[m][1], ahi[m][2], ahi[m][3], b0l, b1l);
                    mma8(acc[m][t], alo[m][0], alo[m][1], alo[m][2], alo[m][3], b0h, b1h);
                }
            }
        }
    }

#pragma unroll
    for (int t = 0; t < NT; t++) {
        int c0 = colbase + t * 8 + 2 * tg;
        float bb0 = bl[c0], bb1 = bl[c0 + 1];
#pragma unroll
        for (int m = 0; m < 2; m++) {
            int r0 = rowbase + m * 16 + g;
            int r1 = r0 + 8;
            float2 v0 = make_float2(acc[m][t][0] + bb0, acc[m][t][1] + bb1);
            float2 v1 = make_float2(acc[m][t][2] + bb0, acc[m][t][3] + bb1);
            if (RELU) {
                v0.x = fmaxf(v0.x, 0.f); v0.y = fmaxf(v0.y, 0.f);
                v1.x = fmaxf(v1.x, 0.f); v1.y = fmaxf(v1.y, 0.f);
            }
            if (r0 < N) *(float2*)&out[(size_t)r0 * DOUT + c0] = v0;
            if (r1 < N) *(float2*)&out[(size_t)r1 * DOUT + c0] = v1;
        }
    }
}

// ---------------------------------------------------------------- launch
extern "C" void kernel_launch(void* const* d_in, const int* in_sizes, int n_in,
                              void* d_out, int out_size) {
    const float4* x4 = (const float4*)d_in[0];
    const int*    ei = (const int*)d_in[1];
    const float *Wl0 = (const float*)d_in[2], *bl0 = (const float*)d_in[3],
                *Wr0 = (const float*)d_in[4];
    const float *Wl1 = (const float*)d_in[5], *bl1 = (const float*)d_in[6],
                *Wr1 = (const float*)d_in[7];
    const float *Wl2 = (const float*)d_in[8], *bl2 = (const float*)d_in[9],
                *Wr2 = (const float*)d_in[10];

    const int N = in_sizes[0] / DFEAT;
    const int E = in_sizes[1] / 2;
    const int* src = ei;
    const int* dst = ei + E;

    const int TB = 256;
    const int eBlocks = (E + TB - 1) / TB;
    const int nBlocks = (N + TB - 1) / TB;
    const int sBlocks = (N + SCAN_TB - 1) / SCAN_TB;
    const int aggBlocks = (N + 7) / 8;
    const int gemmBlocks = (N + 127) / 128;

    // ---- weight pre-split (independent of CSR chain) ----
    presplit_kernel<<<(W_TOTAL + TB - 1) / TB, TB>>>(Wl0, Wr0, Wl1, Wr1, Wl2, Wr2);

    // ---- CSR build (shared across all 3 layers) ----
    zero_cnt_kernel<<<nBlocks, TB>>>(N);
    count_kernel<<<eBlocks, TB>>>(dst, E);
    block_sum_kernel<<<sBlocks, SCAN_TB>>>(N);
    scan_bsum_kernel<<<1, SCAN_TB>>>(sBlocks, N);
    rowptr_kernel<<<sBlocks, SCAN_TB>>>(N);      // rowptr + invdeg + cursor=0
    fill_kernel<<<eBlocks, TB>>>(src, dst, E);

    // ---- layer 0: x -> h1 (relu) ----
    aggregate_csr<<<aggBlocks, TB>>>(x4, 0, N);
    sage_gemm_tc<128, true><<<gemmBlocks, 256>>>(x4, bl0, OFF_WL0, OFF_WR0,
                                                 nullptr, 0, N);

    // ---- layer 1: h1 -> h2 (relu) ----
    aggregate_csr<<<aggBlocks, TB>>>(x4, 1, N);
    sage_gemm_tc<128, true><<<gemmBlocks, 256>>>(x4, bl1, OFF_WL1, OFF_WR1,
                                                 nullptr, 1, N);

    // ---- layer 2: h2 -> out (no relu) ----
    aggregate_csr<<<aggBlocks, TB>>>(x4, 2, N);
    sage_gemm_tc<64, false><<<gemmBlocks, 256>>>(x4, bl2, OFF_WL2, OFF_WR2,
                                                 (float4*)d_out, 2, N);
}